// round 12
// baseline (speedup 1.0000x reference)
#include <cuda_runtime.h>
#include <cuda_bf16.h>
#include <cstdint>

#define BATCH 32
#define NN    512
#define MM    512
#define DD    64
#define LDIAG 1023           // N + M - 1 anti-diagonals
#define BIGF  1e30f
#define LOG2E 1.4426950408889634f
#define LN2   0.6931471805599453f

// Scratch: distance * log2(e) in diagonal layout:
//   g_Ddiag[b][d][r] = LOG2E * D[b][r][d-r],  d = r + j (0-based), r = row.
// 32 * 1023 * 512 * 4B = ~64 MB. Invalid slots never read by the DP.
__device__ float g_Ddiag[(size_t)BATCH * LDIAG * NN];

// ---------------------------------------------------------------------------
// Kernel 1: D for a 128x128 tile, 8x8 register microtile per thread,
// k-major (transposed) smem, norms folded, diagonal-layout coalesced store.
// Stores D * LOG2E so the DP runs natively in the log2 domain.
// ---------------------------------------------------------------------------
#define DIST_SMEM_BYTES (16896 * 4)

__global__ __launch_bounds__(256) void dist_kernel(const float* __restrict__ X,
                                                   const float* __restrict__ Y) {
    extern __shared__ float sm[];
    float* Xs  = sm;                 // [64][128] k-major
    float* Ys  = sm + 64 * 128;      // [64][128] k-major
    float* Dt  = sm;                 // [128][130] (reuses Xs/Ys after barrier)
    float* x2s = sm + 16640;
    float* y2s = x2s + 128;

    const int b  = blockIdx.z;
    const int i0 = blockIdx.y * 128;
    const int j0 = blockIdx.x * 128;
    const int tid = threadIdx.x;

    const float* Xg = X + ((size_t)b * NN + i0) * DD;
    const float* Yg = Y + ((size_t)b * MM + j0) * DD;

    for (int l = tid; l < 128 * 16; l += 256) {
        int kq = l >> 7;
        int r  = l & 127;
        float4 vx = *(const float4*)(Xg + (size_t)r * DD + kq * 4);
        float4 vy = *(const float4*)(Yg + (size_t)r * DD + kq * 4);
        Xs[(kq * 4 + 0) * 128 + r] = vx.x;
        Xs[(kq * 4 + 1) * 128 + r] = vx.y;
        Xs[(kq * 4 + 2) * 128 + r] = vx.z;
        Xs[(kq * 4 + 3) * 128 + r] = vx.w;
        Ys[(kq * 4 + 0) * 128 + r] = vy.x;
        Ys[(kq * 4 + 1) * 128 + r] = vy.y;
        Ys[(kq * 4 + 2) * 128 + r] = vy.z;
        Ys[(kq * 4 + 3) * 128 + r] = vy.w;
    }
    __syncthreads();

    if (tid < 128) {
        float s = 0.0f;
        #pragma unroll 8
        for (int k = 0; k < 64; ++k) { float v = Xs[k * 128 + tid]; s += v * v; }
        x2s[tid] = s;
    } else {
        int c = tid - 128;
        float s = 0.0f;
        #pragma unroll 8
        for (int k = 0; k < 64; ++k) { float v = Ys[k * 128 + c]; s += v * v; }
        y2s[c] = s;
    }

    const int tx = tid & 15, ty = tid >> 4;
    float acc[8][8];
    #pragma unroll
    for (int i = 0; i < 8; i++)
        #pragma unroll
        for (int j = 0; j < 8; j++) acc[i][j] = 0.0f;

    const float* xp = Xs + ty * 8;
    const float* yp = Ys + tx * 8;
    #pragma unroll 4
    for (int k = 0; k < 64; ++k) {
        float4 a0 = *(const float4*)(xp + k * 128);
        float4 a1 = *(const float4*)(xp + k * 128 + 4);
        float4 b0 = *(const float4*)(yp + k * 128);
        float4 b1 = *(const float4*)(yp + k * 128 + 4);
        float av[8] = {a0.x, a0.y, a0.z, a0.w, a1.x, a1.y, a1.z, a1.w};
        float bv[8] = {b0.x, b0.y, b0.z, b0.w, b1.x, b1.y, b1.z, b1.w};
        #pragma unroll
        for (int i = 0; i < 8; i++)
            #pragma unroll
            for (int j = 0; j < 8; j++)
                acc[i][j] += av[i] * bv[j];
    }
    __syncthreads();

    #pragma unroll
    for (int i = 0; i < 8; i++) {
        float xi = x2s[ty * 8 + i];
        #pragma unroll
        for (int j = 0; j < 8; j++)
            Dt[(ty * 8 + i) * 130 + tx * 8 + j] =
                fmaf(-2.0f, acc[i][j], xi + y2s[tx * 8 + j]);
    }
    __syncthreads();

    float* outb = g_Ddiag + (size_t)b * LDIAG * NN;
    const int g  = tid >> 7;
    const int lt = tid & 127;
    for (int t = g; t < 255; t += 2) {
        int lo = t - 127; if (lo < 0) lo = 0;
        int hi = t < 127 ? t : 127;
        int il = lo + lt;
        if (il <= hi)
            outb[(size_t)(i0 + j0 + t) * NN + (i0 + il)] =
                Dt[il * 130 + (t - il)] * LOG2E;
    }
}

// ---------------------------------------------------------------------------
// Kernel 2: soft-DTW DP, BARRIER-FREE asynchronous warp pipeline.
// One CTA per batch, 512 threads; warp w owns rows 32w..32w+31 (1 row/thread,
// state in registers). Adjacent warps hand off seam values through an 8-deep
// smem ring guarded by per-warp progress counters (st.release / ld.acquire).
// D streams via a per-thread cp.async ring (depth 8, wait_group 6).
// Softmin in log2 domain: mn - lg2(1 + ex2(mn-mid) + ex2(mn-mx)).
// ---------------------------------------------------------------------------
__device__ __forceinline__ uint32_t smem_u32(const void* p) {
    uint32_t a;
    asm("{ .reg .u64 t; cvta.to.shared.u64 t, %1; cvt.u32.u64 %0, t; }"
        : "=r"(a) : "l"(p));
    return a;
}
__device__ __forceinline__ int lds_acquire(uint32_t a) {
    int v;
    asm volatile("ld.acquire.cta.shared.b32 %0, [%1];" : "=r"(v) : "r"(a) : "memory");
    return v;
}
__device__ __forceinline__ void sts_release(uint32_t a, int v) {
    asm volatile("st.release.cta.shared.b32 [%0], %1;" :: "r"(a), "r"(v) : "memory");
}
__device__ __forceinline__ int lds_volatile(uint32_t a) {
    int v;
    asm volatile("ld.volatile.shared.b32 %0, [%1];" : "=r"(v) : "r"(a) : "memory");
    return v;
}
__device__ __forceinline__ float ex2f(float x) {
    float r; asm("ex2.approx.f32 %0, %1;" : "=f"(r) : "f"(x)); return r;
}
__device__ __forceinline__ float lg2f(float x) {
    float r; asm("lg2.approx.f32 %0, %1;" : "=f"(r) : "f"(x)); return r;
}

__global__ __launch_bounds__(512) void dp_kernel(float* __restrict__ outp) {
    __shared__ float  ring[8][512];   // [slot][thread]: D for row t at a diagonal
    __shared__ float2 seam[15][8];    // [producer warp][slot d&7] = (R@d, R@d-1) of row 32w+31
    __shared__ int    ctr[16];        // diagonals completed per warp

    const int t    = threadIdx.x;
    const int b    = blockIdx.x;
    const int lane = t & 31;
    const int w    = t >> 5;

    if (t < 16) ctr[t] = 0;

    const float* P = g_Ddiag + (size_t)b * LDIAG * NN;
    const uint32_t ring_t = smem_u32(&ring[0][0]) + (uint32_t)t * 4u;
    const uint32_t ctr_up = smem_u32(&ctr[0]) + (uint32_t)(w - 1) * 4u;  // valid w>0
    const uint32_t ctr_dn = smem_u32(&ctr[0]) + (uint32_t)(w + 1) * 4u;  // used w<15
    const uint32_t ctr_me = smem_u32(&ctr[0]) + (uint32_t)w * 4u;

    // Prologue: prefetch diagonals 0..6 into ring slots 0..6 (one group each).
    #pragma unroll
    for (int d = 0; d < 7; ++d) {
        const float* gp = P + d * 512 + t;
        asm volatile("cp.async.ca.shared.global [%0], [%1], 4;\n"
                     :: "r"(ring_t + (uint32_t)d * 2048u), "l"(gp) : "memory");
        asm volatile("cp.async.commit_group;\n" ::: "memory");
    }
    __syncthreads();                 // counters visible before pipeline starts

    float p1 = BIGF, p2 = BIGF;      // this row at d-1, d-2 (p2 kept for final output)
    float nb1 = BIGF, nb2 = BIGF;    // row t-1 at d-1, d-2

    const int wbase = w << 5;        // first row of this warp

    for (int blk = 0; blk < 128; ++blk) {     // 128 x 8 = 1024 diagonals (1023 real + 1 pad)
        #pragma unroll
        for (int k = 0; k < 8; ++k) {
            const int d = blk * 8 + k;

            // --- upstream seam: lane 0 needs warp w-1 finished diag d-1 ---
            if (w > 0 && lane == 0 && d >= wbase) {
                while (lds_acquire(ctr_up) < d) { }
                float2 s = seam[w - 1][(k - 1) & 7];
                nb1 = s.x; nb2 = s.y;
            }

            asm volatile("cp.async.wait_group 6;\n" ::: "memory");
            float Dv = ring[k][t];

            float cur = BIGF;
            if ((unsigned)(d - t) < (unsigned)MM) {   // j = d - t in [0, M)
                float a, bb;
                if (t == 0) { a = (d == 0) ? 0.0f : BIGF; bb = BIGF; }
                else        { a = nb2;                    bb = nb1; }
                float c   = p1;
                float lo_ = fminf(a, bb), hi_ = fmaxf(a, bb);
                float mn  = fminf(lo_, c);
                float mid = fminf(hi_, fmaxf(lo_, c));
                float mx  = fmaxf(hi_, c);
                float sum = 1.0f + ex2f(mn - mid) + ex2f(mn - mx);
                cur = Dv + mn - lg2f(sum);
            }

            // --- prefetch diag d+7 into slot (k+7)&7 (freed at iter d-1) ---
            {
                int nd = d + 7; if (nd > LDIAG - 1) nd = LDIAG - 1;
                const float* gp = P + (size_t)nd * 512 + t;
                asm volatile("cp.async.ca.shared.global [%0], [%1], 4;\n"
                             :: "r"(ring_t + (uint32_t)((k + 7) & 7) * 2048u), "l"(gp)
                             : "memory");
                asm volatile("cp.async.commit_group;\n" ::: "memory");
            }

            // --- intra-warp handoff (pre-rotation p1) ---
            float u1 = __shfl_up_sync(0xffffffffu, cur, 1);
            float u2 = __shfl_up_sync(0xffffffffu, p1, 1);

            // --- downstream seam publish + progress counter (lane 31) ---
            if (lane == 31) {
                if (w < 15) {
                    // backpressure: slot k was written at d-8; consumer must have
                    // read it (its step d-7 done) before overwrite.
                    while (lds_volatile(ctr_dn) < d - 7) { }
                    seam[w][k] = make_float2(cur, p1);
                }
                sts_release(ctr_me, d + 1);
            }

            p2 = p1; p1 = cur;
            if (lane) { nb1 = u1; nb2 = u2; }
        }
    }

    // After 1024 iters: p1 = cur@1023 (pad, BIGF), p2 = cur@1022 = R[N][M] (log2 units)
    if (t == NN - 1) outp[b] = p2 * LN2;
}

// ---------------------------------------------------------------------------
extern "C" void kernel_launch(void* const* d_in, const int* in_sizes, int n_in,
                              void* d_out, int out_size) {
    const float* X = (const float*)d_in[0];   // [32, 512, 64]
    const float* Y = (const float*)d_in[1];   // [32, 512, 64]
    float* out = (float*)d_out;               // [32]

    cudaFuncSetAttribute(dist_kernel, cudaFuncAttributeMaxDynamicSharedMemorySize,
                         DIST_SMEM_BYTES);

    dist_kernel<<<dim3(MM / 128, NN / 128, BATCH), 256, DIST_SMEM_BYTES>>>(X, Y);
    dp_kernel<<<BATCH, 512>>>(out);
}

// round 13
// speedup vs baseline: 4.4910x; 4.4910x over previous
#include <cuda_runtime.h>
#include <cuda_bf16.h>
#include <cstdint>

#define BATCH 32
#define NN    512
#define MM    512
#define DD    64
#define LDIAG 1023           // N + M - 1 anti-diagonals
#define BIGF  1e30f
#define LOG2E 1.4426950408889634f
#define LN2   0.6931471805599453f

// Scratch: distance * log2(e) in diagonal layout:
//   g_Ddiag[b][d][r] = LOG2E * D[b][r][d-r],  d = r + j (0-based), r = row.
// 32 * 1023 * 512 * 4B = ~64 MB. Invalid slots never read by the DP.
__device__ float g_Ddiag[(size_t)BATCH * LDIAG * NN];

// ---------------------------------------------------------------------------
// Kernel 1: D for a 128x128 tile, 8x8 register microtile per thread,
// k-major (transposed) smem, norms folded, diagonal-layout coalesced store.
// Stores D * LOG2E so the DP runs natively in the log2 domain.
// ---------------------------------------------------------------------------
#define DIST_SMEM_BYTES (16896 * 4)

__global__ __launch_bounds__(256) void dist_kernel(const float* __restrict__ X,
                                                   const float* __restrict__ Y) {
    extern __shared__ float sm[];
    float* Xs  = sm;                 // [64][128] k-major
    float* Ys  = sm + 64 * 128;      // [64][128] k-major
    float* Dt  = sm;                 // [128][130] (reuses Xs/Ys after barrier)
    float* x2s = sm + 16640;
    float* y2s = x2s + 128;

    const int b  = blockIdx.z;
    const int i0 = blockIdx.y * 128;
    const int j0 = blockIdx.x * 128;
    const int tid = threadIdx.x;

    const float* Xg = X + ((size_t)b * NN + i0) * DD;
    const float* Yg = Y + ((size_t)b * MM + j0) * DD;

    for (int l = tid; l < 128 * 16; l += 256) {
        int kq = l >> 7;
        int r  = l & 127;
        float4 vx = *(const float4*)(Xg + (size_t)r * DD + kq * 4);
        float4 vy = *(const float4*)(Yg + (size_t)r * DD + kq * 4);
        Xs[(kq * 4 + 0) * 128 + r] = vx.x;
        Xs[(kq * 4 + 1) * 128 + r] = vx.y;
        Xs[(kq * 4 + 2) * 128 + r] = vx.z;
        Xs[(kq * 4 + 3) * 128 + r] = vx.w;
        Ys[(kq * 4 + 0) * 128 + r] = vy.x;
        Ys[(kq * 4 + 1) * 128 + r] = vy.y;
        Ys[(kq * 4 + 2) * 128 + r] = vy.z;
        Ys[(kq * 4 + 3) * 128 + r] = vy.w;
    }
    __syncthreads();

    if (tid < 128) {
        float s = 0.0f;
        #pragma unroll 8
        for (int k = 0; k < 64; ++k) { float v = Xs[k * 128 + tid]; s += v * v; }
        x2s[tid] = s;
    } else {
        int c = tid - 128;
        float s = 0.0f;
        #pragma unroll 8
        for (int k = 0; k < 64; ++k) { float v = Ys[k * 128 + c]; s += v * v; }
        y2s[c] = s;
    }

    const int tx = tid & 15, ty = tid >> 4;
    float acc[8][8];
    #pragma unroll
    for (int i = 0; i < 8; i++)
        #pragma unroll
        for (int j = 0; j < 8; j++) acc[i][j] = 0.0f;

    const float* xp = Xs + ty * 8;
    const float* yp = Ys + tx * 8;
    #pragma unroll 4
    for (int k = 0; k < 64; ++k) {
        float4 a0 = *(const float4*)(xp + k * 128);
        float4 a1 = *(const float4*)(xp + k * 128 + 4);
        float4 b0 = *(const float4*)(yp + k * 128);
        float4 b1 = *(const float4*)(yp + k * 128 + 4);
        float av[8] = {a0.x, a0.y, a0.z, a0.w, a1.x, a1.y, a1.z, a1.w};
        float bv[8] = {b0.x, b0.y, b0.z, b0.w, b1.x, b1.y, b1.z, b1.w};
        #pragma unroll
        for (int i = 0; i < 8; i++)
            #pragma unroll
            for (int j = 0; j < 8; j++)
                acc[i][j] += av[i] * bv[j];
    }
    __syncthreads();

    #pragma unroll
    for (int i = 0; i < 8; i++) {
        float xi = x2s[ty * 8 + i];
        #pragma unroll
        for (int j = 0; j < 8; j++)
            Dt[(ty * 8 + i) * 130 + tx * 8 + j] =
                fmaf(-2.0f, acc[i][j], xi + y2s[tx * 8 + j]);
    }
    __syncthreads();

    float* outb = g_Ddiag + (size_t)b * LDIAG * NN;
    const int g  = tid >> 7;
    const int lt = tid & 127;
    for (int t = g; t < 255; t += 2) {
        int lo = t - 127; if (lo < 0) lo = 0;
        int hi = t < 127 ? t : 127;
        int il = lo + lt;
        if (il <= hi)
            outb[(size_t)(i0 + j0 + t) * NN + (i0 + il)] =
                Dt[il * 130 + (t - il)] * LOG2E;
    }
}

// ---------------------------------------------------------------------------
// Kernel 2: soft-DTW DP, BLOCK-SKEWED wavefront. One CTA per batch, 512
// threads; warp w owns rows 32w..32w+31 (1 row/thread, register state).
// Block (w, i) = 8 diagonals [8i, 8i+8). Schedule: interval tau runs block
// i = tau - w for each warp (dependency B(w,i) <- B(w-1,i) satisfied by the
// previous interval). ONE __syncthreads per 8 diagonals; intra-block handoff
// is pure shfl; seam = 8 floats/block, parity double-buffered, barrier-ordered.
// D streams via per-thread cp.async double-buffered blocks (wait_group 1).
// Softmin in log2 domain: mn - lg2(1 + ex2(mn-mid) + ex2(mn-mx)).
// ---------------------------------------------------------------------------
__device__ __forceinline__ uint32_t smem_u32(const void* p) {
    uint32_t a;
    asm("{ .reg .u64 t; cvta.to.shared.u64 t, %1; cvt.u32.u64 %0, t; }"
        : "=r"(a) : "l"(p));
    return a;
}
__device__ __forceinline__ float ex2f(float x) {
    float r; asm("ex2.approx.f32 %0, %1;" : "=f"(r) : "f"(x)); return r;
}
__device__ __forceinline__ float lg2f(float x) {
    float r; asm("lg2.approx.f32 %0, %1;" : "=f"(r) : "f"(x)); return r;
}

#define NBLK   128            // 1024 diagonals = 1023 real + 1 pad
#define NINTV  (NBLK + 15)    // skewed intervals

__global__ __launch_bounds__(512) void dp_kernel(float* __restrict__ outp) {
    __shared__ float ring[2][8][512];   // [buf][k][thread]: per-thread-private D
    __shared__ float seam[15][2][8];    // [producer warp][block parity][k]

    const int t    = threadIdx.x;
    const int b    = blockIdx.x;
    const int lane = t & 31;
    const int w    = t >> 5;

    const float* P = g_Ddiag + (size_t)b * LDIAG * NN;
    const uint32_t ring_t = smem_u32(&ring[0][0][0]) + (uint32_t)t * 4u;

    // Prologue: prefetch blocks 0 and 1 (one commit group per block).
    #pragma unroll
    for (int blk = 0; blk < 2; ++blk) {
        #pragma unroll
        for (int k = 0; k < 8; ++k) {
            const float* gp = P + (size_t)(blk * 8 + k) * 512 + t;
            asm volatile("cp.async.ca.shared.global [%0], [%1], 4;\n"
                         :: "r"(ring_t + (uint32_t)(blk * 8 + k) * 2048u), "l"(gp)
                         : "memory");
        }
        asm volatile("cp.async.commit_group;\n" ::: "memory");
    }

    float p1 = BIGF, p2 = BIGF;      // this row at d-1, d-2
    float nb1 = BIGF, nb2 = BIGF;    // row t-1 at d-1, d-2
    __syncthreads();

    for (int tau = 0; tau < NINTV; ++tau) {
        const int i = tau - w;       // this warp's block index this interval
        if ((unsigned)i < (unsigned)NBLK) {
            const int par = i & 1;

            // Block i's D data (group issued 2 blocks ago) must be complete.
            asm volatile("cp.async.wait_group 1;\n" ::: "memory");

            // Lane 0 pulls the upstream seam for this block (written last
            // interval by warp w-1; ordered by the interval barrier).
            float s[8];
            if (lane == 0 && w > 0) {
                float4 lo = *(const float4*)&seam[w - 1][par][0];
                float4 hi = *(const float4*)&seam[w - 1][par][4];
                s[0] = lo.x; s[1] = lo.y; s[2] = lo.z; s[3] = lo.w;
                s[4] = hi.x; s[5] = hi.y; s[6] = hi.z; s[7] = hi.w;
            }

            #pragma unroll
            for (int k = 0; k < 8; ++k) {
                const int d = i * 8 + k;
                float Dv = ring[par][k][t];

                float a, bb;
                if (t == 0) { a = (d == 0) ? 0.0f : BIGF; bb = BIGF; }
                else        { a = nb2;                    bb = nb1; }
                float c = p1;

                float cur = BIGF;
                if ((unsigned)(d - t) < (unsigned)MM) {   // j = d - t in [0, M)
                    float lo_ = fminf(a, bb), hi_ = fmaxf(a, bb);
                    float mn  = fminf(lo_, c);
                    float mid = fminf(hi_, fmaxf(lo_, c));
                    float mx  = fmaxf(hi_, c);
                    float sum = 1.0f + ex2f(mn - mid) + ex2f(mn - mx);
                    cur = Dv + mn - lg2f(sum);
                }

                // Intra-warp handoff (p1 pre-rotation = this row @ d-1).
                float u1 = __shfl_up_sync(0xffffffffu, cur, 1);
                float u2 = __shfl_up_sync(0xffffffffu, p1, 1);

                // Downstream seam publish (consumed next interval).
                if (lane == 31 && w < 15) seam[w][par][k] = cur;

                p2 = p1; p1 = cur;
                if (lane == 0) { nb2 = nb1; nb1 = s[k]; }  // seam window shift
                else           { nb1 = u1;  nb2 = u2;  }
            }

            // Prefetch block i+2 into buffer par (just fully consumed).
            // Always issue (clamped source) to keep group counts uniform.
            #pragma unroll
            for (int k = 0; k < 8; ++k) {
                int d = (i + 2) * 8 + k; if (d > LDIAG - 1) d = LDIAG - 1;
                const float* gp = P + (size_t)d * 512 + t;
                asm volatile("cp.async.ca.shared.global [%0], [%1], 4;\n"
                             :: "r"(ring_t + (uint32_t)(par * 8 + k) * 2048u), "l"(gp)
                             : "memory");
            }
            asm volatile("cp.async.commit_group;\n" ::: "memory");
        }
        __syncthreads();   // orders seam writes (tau) before reads (tau+1)
    }

    // Thread 511: p2 = cur@1022 = R[N][M] (log2 units); diag 1023 is padding.
    if (t == NN - 1) outp[b] = p2 * LN2;
}

// ---------------------------------------------------------------------------
extern "C" void kernel_launch(void* const* d_in, const int* in_sizes, int n_in,
                              void* d_out, int out_size) {
    const float* X = (const float*)d_in[0];   // [32, 512, 64]
    const float* Y = (const float*)d_in[1];   // [32, 512, 64]
    float* out = (float*)d_out;               // [32]

    cudaFuncSetAttribute(dist_kernel, cudaFuncAttributeMaxDynamicSharedMemorySize,
                         DIST_SMEM_BYTES);

    dist_kernel<<<dim3(MM / 128, NN / 128, BATCH), 256, DIST_SMEM_BYTES>>>(X, Y);
    dp_kernel<<<BATCH, 512>>>(out);
}